// round 16
// baseline (speedup 1.0000x reference)
#include <cuda_runtime.h>
#include <cuda_fp16.h>

#define DD 64
#define MAXN 50176
#define MAXE 1310720
#define SCAN_TILE 2048
#define MAX_TILES 32

// Scratch (device globals: no allocation allowed)
__device__ __align__(16) __half2 g_hmsg_h[MAXN * 32]; // fp16 h_msg, 6.4 MB
__device__ __align__(16) float g_hneigh[MAXN * DD];   // 12.8 MB
__device__ float    g_s1[MAXN];
__device__ float    g_s2[MAXN];
__device__ __align__(16) int g_deg[MAXN + 64];
__device__ int      g_base[MAXN + 1];
__device__ int      g_cursor[MAXN];
__device__ int      g_dst[MAXE];
__device__ unsigned g_pk[MAXE];             // src | biasbit<<31 (edge order)
__device__ __align__(8) uint2 g_edge[MAXE]; // (src, e) sorted by dst
__device__ int      g_part[MAX_TILES];
__device__ int      g_partflag[MAX_TILES];
__device__ int      g_scan_done;
__device__ int      g_is64;

// ---------------------------------------------------------------------------
// K1: tiled SGEMM (128 nodes x 64 dims, 256 thr, 8x4 microtile) PLUS:
//   per-block v1/v2/c1/c2, s1/s2, deg zeroing; block 0: scan state + probe.
// ---------------------------------------------------------------------------
__global__ void __launch_bounds__(256) k1_node_pre(
    const float* __restrict__ feat,
    const float* __restrict__ W1w, const float* __restrict__ W1b,
    const float* __restrict__ Wattw, const float* __restrict__ Wattb,
    const float* __restrict__ a, const int* __restrict__ rawidx,
    int twoE, int N)
{
    __shared__ float fs[64][132];  // fs[k][node]
    __shared__ float ws[64][68];   // ws[k][d]
    __shared__ float v1s[64], v2s[64], biass[64];
    __shared__ float cc[2];

    int t = threadIdx.x;
    int n0 = blockIdx.x * 128;

    if (t < 128 && n0 + t < N) g_deg[n0 + t] = 0;
    if (blockIdx.x == 0) {
        if (t >= 128 && t < 128 + MAX_TILES) {
            g_part[t - 128] = 0;
            g_partflag[t - 128] = 0;
        }
        if (t == 160) g_scan_done = 0;
        if (t == 161) {
            unsigned o = 0;
            int n = min(twoE, 2048);
            for (int k = 1; k < n; k += 2) o |= (unsigned)rawidx[k];
            g_is64 = (o == 0) ? 1 : 0;
        }
    }

    for (int i = t; i < 1024; i += 256) {
        int r = i >> 4;
        int c4 = (i & 15) * 4;
        float4 wv = reinterpret_cast<const float4*>(W1w)[i];
        ws[c4 + 0][r] = wv.x; ws[c4 + 1][r] = wv.y;
        ws[c4 + 2][r] = wv.z; ws[c4 + 3][r] = wv.w;
    }
    for (int i = t; i < 2048; i += 256) {
        int r = i >> 4;
        int c4 = (i & 15) * 4;
        float4 fv = make_float4(0.f, 0.f, 0.f, 0.f);
        if (n0 + r < N)
            fv = reinterpret_cast<const float4*>(feat)[(n0 + r) * 16 + (i & 15)];
        fs[c4 + 0][r] = fv.x; fs[c4 + 1][r] = fv.y;
        fs[c4 + 2][r] = fv.z; fs[c4 + 3][r] = fv.w;
    }
    if (t < 64) {
        float v1 = 0.f, v2 = 0.f;
        for (int dd = 0; dd < 64; dd++) {
            float w = Wattw[dd * 64 + t];
            v1 += w * a[dd];
            v2 += w * a[64 + dd];
        }
        v1s[t] = v1; v2s[t] = v2; biass[t] = W1b[t];
    } else if (t == 64) {
        float c1 = 0.f, c2 = 0.f;
        for (int dd = 0; dd < 64; dd++) {
            float b = Wattb[dd];
            c1 += b * a[dd];
            c2 += b * a[64 + dd];
        }
        cc[0] = c1; cc[1] = c2;
    }
    __syncthreads();

    {
        int n = t & 127;
        if (n0 + n < N) {
            const float* vv = (t < 128) ? v1s : v2s;
            float s = cc[t >> 7];
#pragma unroll 16
            for (int k = 0; k < 64; k++) s += fs[k][n] * vv[k];
            if (t < 128) g_s1[n0 + n] = s; else g_s2[n0 + n] = s;
        }
    }

    int tx = t & 15, ty = t >> 4;
    float acc[8][4];
#pragma unroll
    for (int i = 0; i < 8; i++)
#pragma unroll
        for (int j = 0; j < 4; j++) acc[i][j] = biass[tx * 4 + j];

#pragma unroll 4
    for (int k = 0; k < 64; k++) {
        float4 b  = *reinterpret_cast<const float4*>(&ws[k][tx * 4]);
        float4 a0 = *reinterpret_cast<const float4*>(&fs[k][ty * 8]);
        float4 a1 = *reinterpret_cast<const float4*>(&fs[k][ty * 8 + 4]);
        float av[8] = {a0.x, a0.y, a0.z, a0.w, a1.x, a1.y, a1.z, a1.w};
#pragma unroll
        for (int i = 0; i < 8; i++) {
            acc[i][0] += av[i] * b.x; acc[i][1] += av[i] * b.y;
            acc[i][2] += av[i] * b.z; acc[i][3] += av[i] * b.w;
        }
    }

#pragma unroll
    for (int i = 0; i < 8; i++) {
        int n = n0 + ty * 8 + i;
        if (n < N) {
            g_hmsg_h[n * 32 + tx * 2]     = __floats2half2_rn(acc[i][0], acc[i][1]);
            g_hmsg_h[n * 32 + tx * 2 + 1] = __floats2half2_rn(acc[i][2], acc[i][3]);
        }
    }
}

// ---------------------------------------------------------------------------
// K2: canonicalize edges (2 per thread, vectorized) + degree histogram.
// ---------------------------------------------------------------------------
__global__ void k2_canon(const void* __restrict__ idxv,
                         const void* __restrict__ etv, int E, int N)
{
    int i = (blockIdx.x * blockDim.x + threadIdx.x) * 2;
    if (i >= E) return;
    int s0, s1v, d0, d1v; long long et0, et1;
    bool two = (i + 1 < E);
    if (g_is64) {
        const long long* ix = (const long long*)idxv;
        const long long* ev = (const long long*)etv;
        longlong2 sp = *reinterpret_cast<const longlong2*>(&ix[i]);
        longlong2 dp = *reinterpret_cast<const longlong2*>(&ix[E + i]);
        longlong2 ep = *reinterpret_cast<const longlong2*>(&ev[i]);
        s0 = (int)sp.x; s1v = (int)sp.y;
        d0 = (int)dp.x; d1v = (int)dp.y;
        et0 = ep.x; et1 = ep.y;
    } else {
        const int* ix = (const int*)idxv;
        const int* ev = (const int*)etv;
        int2 sp = *reinterpret_cast<const int2*>(&ix[i]);
        int2 dp = *reinterpret_cast<const int2*>(&ix[E + i]);
        int2 ep = *reinterpret_cast<const int2*>(&ev[i]);
        s0 = sp.x; s1v = sp.y;
        d0 = dp.x; d1v = dp.y;
        et0 = ep.x; et1 = ep.y;
    }
    s0 = min(max(s0, 0), N - 1);
    d0 = min(max(d0, 0), N - 1);
    g_pk[i]  = (unsigned)s0 | ((et0 == 0) ? 0x80000000u : 0u);
    g_dst[i] = d0;
    atomicAdd(&g_deg[d0], 1);
    if (two) {
        s1v = min(max(s1v, 0), N - 1);
        d1v = min(max(d1v, 0), N - 1);
        g_pk[i + 1]  = (unsigned)s1v | ((et1 == 0) ? 0x80000000u : 0u);
        g_dst[i + 1] = d1v;
        atomicAdd(&g_deg[d1v], 1);
    }
}

// ---------------------------------------------------------------------------
// K4: embedded scan (bid < ntiles, decoupled lookback) + spin + fill.
// ---------------------------------------------------------------------------
__global__ void __launch_bounds__(256) k4_scanfill(int E, int N, int ntiles)
{
    int t = threadIdx.x;
    int bid = blockIdx.x;

    if (bid < ntiles) {
        __shared__ int warptot[8];
        __shared__ int tileoff;
        int lane = t & 31, wid = t >> 5;
        int i0 = bid * SCAN_TILE + t * 8;

        int d[8];
        int4 p0 = *reinterpret_cast<const int4*>(&g_deg[i0]);
        int4 p1 = *reinterpret_cast<const int4*>(&g_deg[i0 + 4]);
        d[0]=p0.x; d[1]=p0.y; d[2]=p0.z; d[3]=p0.w;
        d[4]=p1.x; d[5]=p1.y; d[6]=p1.z; d[7]=p1.w;

        int s = 0;
#pragma unroll
        for (int k = 0; k < 8; k++) s += (i0 + k < N) ? d[k] : 0;

        int inc = s;
#pragma unroll
        for (int off = 1; off < 32; off <<= 1) {
            int u = __shfl_up_sync(0xffffffffu, inc, off);
            if (lane >= off) inc += u;
        }
        if (lane == 31) warptot[wid] = inc;
        __syncthreads();
        if (t < 8) {
            int v = warptot[t];
            int iv = v;
#pragma unroll
            for (int off = 1; off < 8; off <<= 1) {
                int u = __shfl_up_sync(0xffu, iv, off);
                if (t >= off) iv += u;
            }
            warptot[t] = iv - v;
            if (t == 7) {
                g_part[bid] = iv;
                __threadfence();
                ((volatile int*)g_partflag)[bid] = 1;
            }
        }
        __syncthreads();

        if (t < 32) {
            int v = 0;
            if (t < bid) {
                while (((volatile int*)g_partflag)[t] == 0) { }
                v = g_part[t];
            }
#pragma unroll
            for (int off = 16; off > 0; off >>= 1)
                v += __shfl_down_sync(0xffffffffu, v, off);
            if (t == 0) tileoff = v;
        }
        __syncthreads();

        int b = tileoff + warptot[wid] + (inc - s);
#pragma unroll
        for (int k = 0; k < 8; k++) {
            int i = i0 + k;
            if (i < N) {
                g_base[i]   = b;
                g_cursor[i] = b;
                b += d[k];
            }
        }
        __syncthreads();
        __threadfence();
        if (t == 0) atomicAdd(&g_scan_done, 1);
    }

    if (t == 0) {
        while (((volatile int*)&g_scan_done)[0] < ntiles) { }
    }
    __syncthreads();

    int i = bid * 256 + t;
    if (i >= E) return;
    int d2 = g_dst[i];
    unsigned p = g_pk[i];
    int src = (int)(p & 0x7FFFFFFFu);
    float e = (g_s1[src] + g_s2[d2] + ((p >> 31) ? 5.0f : 0.0f)) * 0.125f;
    e = (e > 0.f) ? e : 0.2f * e;
    int pos = atomicAdd(&g_cursor[d2], 1);
    g_edge[pos] = make_uint2((unsigned)src, __float_as_uint(e));
}

// ---------------------------------------------------------------------------
// K5: warp-per-node gather, quarter-warp-per-edge.
// Lane = (q, sub): q = lane>>3 selects edge within a 4-edge group, sub =
// lane&7 selects 8 dims (uint4 = 4x half2, LDG.128). One warp covers 4
// edges/step, unrolled x2 (8 in flight). Combine via shfl_xor(8,16);
// lanes 0-7 store two float4s. No max-subtraction (bounded scores).
// ---------------------------------------------------------------------------
__global__ void __launch_bounds__(256) k5_gather(int N)
{
    __shared__ uint2 stage[8][32];
    int warp = threadIdx.x >> 5;
    int lane = threadIdx.x & 31;
    int q   = lane >> 3;        // edge slot within 4-edge group
    int sub = lane & 7;         // dim group (8 dims)
    int v = blockIdx.x * 8 + warp;
    if (v >= N) return;

    int base = g_base[v];
    int deg  = g_deg[v];
    const uint4* hm = reinterpret_cast<const uint4*>(g_hmsg_h);

    float sum = 0.f;
    float acc[8] = {0.f, 0.f, 0.f, 0.f, 0.f, 0.f, 0.f, 0.f};
    for (int j0 = 0; j0 < deg; j0 += 32) {
        int nj = min(32, deg - j0);
        if (lane < nj) {
            uint2 t = g_edge[base + j0 + lane];
            float ex = __expf(__uint_as_float(t.y));
            sum += ex;
            stage[warp][lane] = make_uint2(t.x, __float_as_uint(ex));
        }
        __syncwarp();
        int jj = 0;
        for (; jj + 8 <= nj; jj += 8) {
            uint2 e0 = stage[warp][jj + q];
            uint2 e1 = stage[warp][jj + 4 + q];
            uint4 h0 = hm[e0.x * 8 + sub];
            uint4 h1 = hm[e1.x * 8 + sub];
            float a0 = __uint_as_float(e0.y);
            float a1 = __uint_as_float(e1.y);
            float2 p00 = __half22float2(*reinterpret_cast<__half2*>(&h0.x));
            float2 p01 = __half22float2(*reinterpret_cast<__half2*>(&h0.y));
            float2 p02 = __half22float2(*reinterpret_cast<__half2*>(&h0.z));
            float2 p03 = __half22float2(*reinterpret_cast<__half2*>(&h0.w));
            float2 p10 = __half22float2(*reinterpret_cast<__half2*>(&h1.x));
            float2 p11 = __half22float2(*reinterpret_cast<__half2*>(&h1.y));
            float2 p12 = __half22float2(*reinterpret_cast<__half2*>(&h1.z));
            float2 p13 = __half22float2(*reinterpret_cast<__half2*>(&h1.w));
            acc[0] += a0 * p00.x + a1 * p10.x;
            acc[1] += a0 * p00.y + a1 * p10.y;
            acc[2] += a0 * p01.x + a1 * p11.x;
            acc[3] += a0 * p01.y + a1 * p11.y;
            acc[4] += a0 * p02.x + a1 * p12.x;
            acc[5] += a0 * p02.y + a1 * p12.y;
            acc[6] += a0 * p03.x + a1 * p13.x;
            acc[7] += a0 * p03.y + a1 * p13.y;
        }
        for (; jj < nj; jj += 4) {
            int e_idx = jj + q;
            if (e_idx < nj) {
                uint2 e0 = stage[warp][e_idx];
                uint4 h0 = hm[e0.x * 8 + sub];
                float a0 = __uint_as_float(e0.y);
                float2 p00 = __half22float2(*reinterpret_cast<__half2*>(&h0.x));
                float2 p01 = __half22float2(*reinterpret_cast<__half2*>(&h0.y));
                float2 p02 = __half22float2(*reinterpret_cast<__half2*>(&h0.z));
                float2 p03 = __half22float2(*reinterpret_cast<__half2*>(&h0.w));
                acc[0] += a0 * p00.x; acc[1] += a0 * p00.y;
                acc[2] += a0 * p01.x; acc[3] += a0 * p01.y;
                acc[4] += a0 * p02.x; acc[5] += a0 * p02.y;
                acc[6] += a0 * p03.x; acc[7] += a0 * p03.y;
            }
        }
        __syncwarp();
    }

    // combine the 4 quarter-warp edge partitions (same dims)
#pragma unroll
    for (int i = 0; i < 8; i++) {
        acc[i] += __shfl_xor_sync(0xffffffffu, acc[i], 8);
        acc[i] += __shfl_xor_sync(0xffffffffu, acc[i], 16);
    }

#pragma unroll
    for (int off = 16; off > 0; off >>= 1)
        sum += __shfl_xor_sync(0xffffffffu, sum, off);
    float inv = 1.0f / (sum + 1e-9f);

    if (q == 0) {
        float4* out = reinterpret_cast<float4*>(&g_hneigh[v * 64 + sub * 8]);
        out[0] = make_float4(acc[0] * inv, acc[1] * inv, acc[2] * inv, acc[3] * inv);
        out[1] = make_float4(acc[4] * inv, acc[5] * inv, acc[6] * inv, acc[7] * inv);
    }
}

// ---------------------------------------------------------------------------
// K6 (tiled SGEMM): 128x64 tile, 256 threads, 8x4 microtile.
// ---------------------------------------------------------------------------
__global__ void __launch_bounds__(256) k6_out(
    const float* __restrict__ feat,
    const float* __restrict__ W2w, const float* __restrict__ W2b,
    float* __restrict__ out, int N)
{
    __shared__ float ps[64][132];
    __shared__ float ws[64][68];
    __shared__ float biass[64];

    int t = threadIdx.x;
    int n0 = blockIdx.x * 128;

    for (int i = t; i < 1024; i += 256) {
        int r = i >> 4;
        int c4 = (i & 15) * 4;
        float4 wv = reinterpret_cast<const float4*>(W2w)[i];
        ws[c4 + 0][r] = wv.x; ws[c4 + 1][r] = wv.y;
        ws[c4 + 2][r] = wv.z; ws[c4 + 3][r] = wv.w;
    }
    for (int i = t; i < 2048; i += 256) {
        int r = i >> 4;
        int c4 = (i & 15) * 4;
        float4 fv = make_float4(0.f, 0.f, 0.f, 0.f);
        float4 hv = make_float4(0.f, 0.f, 0.f, 0.f);
        if (n0 + r < N) {
            fv = reinterpret_cast<const float4*>(feat)[(n0 + r) * 16 + (i & 15)];
            hv = reinterpret_cast<const float4*>(g_hneigh)[(n0 + r) * 16 + (i & 15)];
        }
        ps[c4 + 0][r] = fv.x * hv.x; ps[c4 + 1][r] = fv.y * hv.y;
        ps[c4 + 2][r] = fv.z * hv.z; ps[c4 + 3][r] = fv.w * hv.w;
    }
    if (t < 64) biass[t] = W2b[t];
    __syncthreads();

    int tx = t & 15, ty = t >> 4;
    float acc[8][4];
#pragma unroll
    for (int i = 0; i < 8; i++)
#pragma unroll
        for (int j = 0; j < 4; j++) acc[i][j] = biass[tx * 4 + j];

#pragma unroll 4
    for (int k = 0; k < 64; k++) {
        float4 b  = *reinterpret_cast<const float4*>(&ws[k][tx * 4]);
        float4 a0 = *reinterpret_cast<const float4*>(&ps[k][ty * 8]);
        float4 a1 = *reinterpret_cast<const float4*>(&ps[k][ty * 8 + 4]);
        float av[8] = {a0.x, a0.y, a0.z, a0.w, a1.x, a1.y, a1.z, a1.w};
#pragma unroll
        for (int i = 0; i < 8; i++) {
            acc[i][0] += av[i] * b.x; acc[i][1] += av[i] * b.y;
            acc[i][2] += av[i] * b.z; acc[i][3] += av[i] * b.w;
        }
    }

#pragma unroll
    for (int i = 0; i < 8; i++) {
        int n = n0 + ty * 8 + i;
        if (n < N) {
            float4 f = reinterpret_cast<const float4*>(feat)[n * 16 + tx];
            float4 h = reinterpret_cast<const float4*>(g_hneigh)[n * 16 + tx];
            float o0 = f.x + h.x + acc[i][0];
            float o1 = f.y + h.y + acc[i][1];
            float o2 = f.z + h.z + acc[i][2];
            float o3 = f.w + h.w + acc[i][3];
            o0 = (o0 > 0.f) ? o0 : 0.2f * o0;
            o1 = (o1 > 0.f) ? o1 : 0.2f * o1;
            o2 = (o2 > 0.f) ? o2 : 0.2f * o2;
            o3 = (o3 > 0.f) ? o3 : 0.2f * o3;
            reinterpret_cast<float4*>(out)[n * 16 + tx] = make_float4(o0, o1, o2, o3);
        }
    }
}

// ---------------------------------------------------------------------------
// Launch. Inputs identified by SIZE (robust to scalar materialization).
// ---------------------------------------------------------------------------
extern "C" void kernel_launch(void* const* d_in, const int* in_sizes, int n_in,
                              void* d_out, int out_size)
{
    const void  *idx = nullptr, *etype = nullptr;
    const float *feat = nullptr;
    const float *Wmat[3] = {nullptr, nullptr, nullptr};
    const float *Wb[3]   = {nullptr, nullptr, nullptr};
    const float *a = nullptr;
    int nm = 0, nb = 0;

    int big[8]; int nbig = 0;
    for (int i = 0; i < n_in; i++) {
        int s = in_sizes[i];
        if (s > 4096) { if (nbig < 8) big[nbig++] = i; }
        else if (s == 4096) { if (nm < 3) Wmat[nm++] = (const float*)d_in[i]; }
        else if (s == 128)  { a = (const float*)d_in[i]; }
        else if (s == 64)   { if (nb < 3) Wb[nb++] = (const float*)d_in[i]; }
    }
    for (int x = 0; x < nbig; x++)
        for (int y = 0; y < nbig; y++)
            if (x != y && in_sizes[big[x]] == 2 * in_sizes[big[y]]) {
                idx = d_in[big[x]]; etype = d_in[big[y]];
            }
    for (int x = 0; x < nbig; x++)
        if (d_in[big[x]] != idx && d_in[big[x]] != etype)
            feat = (const float*)d_in[big[x]];

    const float *W1w = Wmat[0], *W2w = Wmat[1], *Wattw = Wmat[2];
    const float *W1b = Wb[0],   *W2b = Wb[1],   *Wattb = Wb[2];

    int E = 0, N = 0;
    for (int x = 0; x < nbig; x++) {
        if (d_in[big[x]] == etype) E = in_sizes[big[x]];
        if ((const float*)d_in[big[x]] == feat) N = in_sizes[big[x]] / DD;
    }
    if (!idx || !etype || !feat || E <= 0 || N <= 0) return;

    int eb = (E + 255) / 256;
    int e2b = (E + 511) / 512;
    int gemb = (N + 127) / 128;
    int ntiles = (N + SCAN_TILE - 1) / SCAN_TILE;

    k1_node_pre<<<gemb, 256>>>(feat, W1w, W1b, Wattw, Wattb, a,
                               (const int*)idx, 2 * E, N);   // #1
    k2_canon<<<e2b, 256>>>(idx, etype, E, N);                // #2
    k4_scanfill<<<eb, 256>>>(E, N, ntiles);                  // #3
    k5_gather<<<(N + 7) / 8, 256>>>(N);                      // #4 (profiled)
    k6_out<<<gemb, 256>>>(feat, W2w, W2b, (float*)d_out, N); // #5
}

// round 17
// speedup vs baseline: 1.0147x; 1.0147x over previous
#include <cuda_runtime.h>
#include <cuda_fp16.h>

#define DD 64
#define MAXN 50176
#define MAXE 1310720
#define SCAN_TILE 2048
#define MAX_TILES 32

// Scratch (device globals: no allocation allowed)
__device__ __align__(16) __half2 g_hmsg_h[MAXN * 32]; // fp16 h_msg, 6.4 MB
__device__ __align__(16) float g_hneigh[MAXN * DD];   // 12.8 MB
__device__ float    g_s1[MAXN];
__device__ float    g_s2[MAXN];
__device__ __align__(16) int g_deg[MAXN + 64];
__device__ int      g_base[MAXN + 1];
__device__ int      g_cursor[MAXN];
__device__ __align__(8) uint2 g_edge[MAXE]; // (src, e) sorted by dst
__device__ int      g_part[MAX_TILES];
__device__ int      g_partflag[MAX_TILES];
__device__ int      g_scan_done;
__device__ int      g_is64;

// ---------------------------------------------------------------------------
// K1: tiled SGEMM (128 nodes x 64 dims, 256 thr, 8x4 microtile) PLUS:
//   per-block v1/v2/c1/c2, s1/s2, deg zeroing; block 0: scan state + probe.
// ---------------------------------------------------------------------------
__global__ void __launch_bounds__(256) k1_node_pre(
    const float* __restrict__ feat,
    const float* __restrict__ W1w, const float* __restrict__ W1b,
    const float* __restrict__ Wattw, const float* __restrict__ Wattb,
    const float* __restrict__ a, const int* __restrict__ rawidx,
    int twoE, int N)
{
    __shared__ float fs[64][132];  // fs[k][node]
    __shared__ float ws[64][68];   // ws[k][d]
    __shared__ float v1s[64], v2s[64], biass[64];
    __shared__ float cc[2];

    int t = threadIdx.x;
    int n0 = blockIdx.x * 128;

    if (t < 128 && n0 + t < N) g_deg[n0 + t] = 0;
    if (blockIdx.x == 0) {
        if (t >= 128 && t < 128 + MAX_TILES) {
            g_part[t - 128] = 0;
            g_partflag[t - 128] = 0;
        }
        if (t == 160) g_scan_done = 0;
        if (t == 161) {
            unsigned o = 0;
            int n = min(twoE, 2048);
            for (int k = 1; k < n; k += 2) o |= (unsigned)rawidx[k];
            g_is64 = (o == 0) ? 1 : 0;
        }
    }

    for (int i = t; i < 1024; i += 256) {
        int r = i >> 4;
        int c4 = (i & 15) * 4;
        float4 wv = reinterpret_cast<const float4*>(W1w)[i];
        ws[c4 + 0][r] = wv.x; ws[c4 + 1][r] = wv.y;
        ws[c4 + 2][r] = wv.z; ws[c4 + 3][r] = wv.w;
    }
    for (int i = t; i < 2048; i += 256) {
        int r = i >> 4;
        int c4 = (i & 15) * 4;
        float4 fv = make_float4(0.f, 0.f, 0.f, 0.f);
        if (n0 + r < N)
            fv = reinterpret_cast<const float4*>(feat)[(n0 + r) * 16 + (i & 15)];
        fs[c4 + 0][r] = fv.x; fs[c4 + 1][r] = fv.y;
        fs[c4 + 2][r] = fv.z; fs[c4 + 3][r] = fv.w;
    }
    if (t < 64) {
        float v1 = 0.f, v2 = 0.f;
        for (int dd = 0; dd < 64; dd++) {
            float w = Wattw[dd * 64 + t];
            v1 += w * a[dd];
            v2 += w * a[64 + dd];
        }
        v1s[t] = v1; v2s[t] = v2; biass[t] = W1b[t];
    } else if (t == 64) {
        float c1 = 0.f, c2 = 0.f;
        for (int dd = 0; dd < 64; dd++) {
            float b = Wattb[dd];
            c1 += b * a[dd];
            c2 += b * a[64 + dd];
        }
        cc[0] = c1; cc[1] = c2;
    }
    __syncthreads();

    {
        int n = t & 127;
        if (n0 + n < N) {
            const float* vv = (t < 128) ? v1s : v2s;
            float s = cc[t >> 7];
#pragma unroll 16
            for (int k = 0; k < 64; k++) s += fs[k][n] * vv[k];
            if (t < 128) g_s1[n0 + n] = s; else g_s2[n0 + n] = s;
        }
    }

    int tx = t & 15, ty = t >> 4;
    float acc[8][4];
#pragma unroll
    for (int i = 0; i < 8; i++)
#pragma unroll
        for (int j = 0; j < 4; j++) acc[i][j] = biass[tx * 4 + j];

#pragma unroll 4
    for (int k = 0; k < 64; k++) {
        float4 b  = *reinterpret_cast<const float4*>(&ws[k][tx * 4]);
        float4 a0 = *reinterpret_cast<const float4*>(&fs[k][ty * 8]);
        float4 a1 = *reinterpret_cast<const float4*>(&fs[k][ty * 8 + 4]);
        float av[8] = {a0.x, a0.y, a0.z, a0.w, a1.x, a1.y, a1.z, a1.w};
#pragma unroll
        for (int i = 0; i < 8; i++) {
            acc[i][0] += av[i] * b.x; acc[i][1] += av[i] * b.y;
            acc[i][2] += av[i] * b.z; acc[i][3] += av[i] * b.w;
        }
    }

#pragma unroll
    for (int i = 0; i < 8; i++) {
        int n = n0 + ty * 8 + i;
        if (n < N) {
            g_hmsg_h[n * 32 + tx * 2]     = __floats2half2_rn(acc[i][0], acc[i][1]);
            g_hmsg_h[n * 32 + tx * 2 + 1] = __floats2half2_rn(acc[i][2], acc[i][3]);
        }
    }
}

// ---------------------------------------------------------------------------
// K2: pure degree histogram (reads ONLY the dst half of indices).
// ---------------------------------------------------------------------------
__global__ void k2_hist(const void* __restrict__ idxv, int E, int N)
{
    int i = (blockIdx.x * blockDim.x + threadIdx.x) * 2;
    if (i >= E) return;
    int d0, d1v;
    bool two = (i + 1 < E);
    if (g_is64) {
        longlong2 dp = *reinterpret_cast<const longlong2*>(
            &((const long long*)idxv)[E + i]);
        d0 = (int)dp.x; d1v = (int)dp.y;
    } else {
        int2 dp = *reinterpret_cast<const int2*>(&((const int*)idxv)[E + i]);
        d0 = dp.x; d1v = dp.y;
    }
    d0 = min(max(d0, 0), N - 1);
    atomicAdd(&g_deg[d0], 1);
    if (two) {
        d1v = min(max(d1v, 0), N - 1);
        atomicAdd(&g_deg[d1v], 1);
    }
}

// ---------------------------------------------------------------------------
// K4: embedded scan (bid < ntiles, decoupled lookback) + spin + fill.
// Fill reads RAW src/dst/etype (no intermediates), computes e, counting-sorts
// (src, e) into g_edge.
// ---------------------------------------------------------------------------
__global__ void __launch_bounds__(256) k4_scanfill(
    const void* __restrict__ idxv, const void* __restrict__ etv,
    int E, int N, int ntiles)
{
    int t = threadIdx.x;
    int bid = blockIdx.x;

    if (bid < ntiles) {
        __shared__ int warptot[8];
        __shared__ int tileoff;
        int lane = t & 31, wid = t >> 5;
        int i0 = bid * SCAN_TILE + t * 8;

        int d[8];
        int4 p0 = *reinterpret_cast<const int4*>(&g_deg[i0]);
        int4 p1 = *reinterpret_cast<const int4*>(&g_deg[i0 + 4]);
        d[0]=p0.x; d[1]=p0.y; d[2]=p0.z; d[3]=p0.w;
        d[4]=p1.x; d[5]=p1.y; d[6]=p1.z; d[7]=p1.w;

        int s = 0;
#pragma unroll
        for (int k = 0; k < 8; k++) s += (i0 + k < N) ? d[k] : 0;

        int inc = s;
#pragma unroll
        for (int off = 1; off < 32; off <<= 1) {
            int u = __shfl_up_sync(0xffffffffu, inc, off);
            if (lane >= off) inc += u;
        }
        if (lane == 31) warptot[wid] = inc;
        __syncthreads();
        if (t < 8) {
            int v = warptot[t];
            int iv = v;
#pragma unroll
            for (int off = 1; off < 8; off <<= 1) {
                int u = __shfl_up_sync(0xffu, iv, off);
                if (t >= off) iv += u;
            }
            warptot[t] = iv - v;
            if (t == 7) {
                g_part[bid] = iv;
                __threadfence();
                ((volatile int*)g_partflag)[bid] = 1;
            }
        }
        __syncthreads();

        if (t < 32) {
            int v = 0;
            if (t < bid) {
                while (((volatile int*)g_partflag)[t] == 0) { }
                v = g_part[t];
            }
#pragma unroll
            for (int off = 16; off > 0; off >>= 1)
                v += __shfl_down_sync(0xffffffffu, v, off);
            if (t == 0) tileoff = v;
        }
        __syncthreads();

        int b = tileoff + warptot[wid] + (inc - s);
#pragma unroll
        for (int k = 0; k < 8; k++) {
            int i = i0 + k;
            if (i < N) {
                g_base[i]   = b;
                g_cursor[i] = b;
                b += d[k];
            }
        }
        __syncthreads();
        __threadfence();
        if (t == 0) atomicAdd(&g_scan_done, 1);
    }

    if (t == 0) {
        while (((volatile int*)&g_scan_done)[0] < ntiles) { }
    }
    __syncthreads();

    int i = bid * 256 + t;
    if (i >= E) return;
    int src, d2; long long et;
    if (g_is64) {
        src = (int)((const long long*)idxv)[i];
        d2  = (int)((const long long*)idxv)[E + i];
        et  = ((const long long*)etv)[i];
    } else {
        src = ((const int*)idxv)[i];
        d2  = ((const int*)idxv)[E + i];
        et  = ((const int*)etv)[i];
    }
    src = min(max(src, 0), N - 1);
    d2  = min(max(d2, 0), N - 1);
    float e = (g_s1[src] + g_s2[d2] + ((et == 0) ? 5.0f : 0.0f)) * 0.125f;
    e = (e > 0.f) ? e : 0.2f * e;
    int pos = atomicAdd(&g_cursor[d2], 1);
    g_edge[pos] = make_uint2((unsigned)src, __float_as_uint(e));
}

// ---------------------------------------------------------------------------
// K5 (R15 version): warp-per-node gather, half-warp-per-edge.
// Lanes 0-15 / 16-31 process different staged edges; each lane loads uint2
// (4 dims, LDG.64). Unrolled x2. Combine via shfl_xor(16); lanes 0-15 store
// float4. No max-subtraction (bounded scores).
// ---------------------------------------------------------------------------
__global__ void __launch_bounds__(256) k5_gather(int N)
{
    __shared__ uint2 stage[8][32];
    int warp = threadIdx.x >> 5;
    int lane = threadIdx.x & 31;
    int half = lane >> 4;
    int sub  = lane & 15;
    int v = blockIdx.x * 8 + warp;
    if (v >= N) return;

    int base = g_base[v];
    int deg  = g_deg[v];
    const uint2* hm = reinterpret_cast<const uint2*>(g_hmsg_h);

    float sum = 0.f;
    float4 acc = make_float4(0.f, 0.f, 0.f, 0.f);
    for (int j0 = 0; j0 < deg; j0 += 32) {
        int nj = min(32, deg - j0);
        if (lane < nj) {
            uint2 t = g_edge[base + j0 + lane];
            float ex = __expf(__uint_as_float(t.y));
            sum += ex;
            stage[warp][lane] = make_uint2(t.x, __float_as_uint(ex));
        }
        __syncwarp();
        int jj = 0;
        for (; jj + 4 <= nj; jj += 4) {
            uint2 e0 = stage[warp][jj + half];
            uint2 e1 = stage[warp][jj + 2 + half];
            uint2 h0 = hm[e0.x * 16 + sub];
            uint2 h1 = hm[e1.x * 16 + sub];
            float a0 = __uint_as_float(e0.y);
            float a1 = __uint_as_float(e1.y);
            float2 l0 = __half22float2(*reinterpret_cast<__half2*>(&h0.x));
            float2 u0 = __half22float2(*reinterpret_cast<__half2*>(&h0.y));
            float2 l1 = __half22float2(*reinterpret_cast<__half2*>(&h1.x));
            float2 u1 = __half22float2(*reinterpret_cast<__half2*>(&h1.y));
            acc.x += a0 * l0.x + a1 * l1.x;
            acc.y += a0 * l0.y + a1 * l1.y;
            acc.z += a0 * u0.x + a1 * u1.x;
            acc.w += a0 * u0.y + a1 * u1.y;
        }
        for (; jj < nj; jj += 2) {
            int e_idx = jj + half;
            if (e_idx < nj) {
                uint2 e0 = stage[warp][e_idx];
                uint2 h0 = hm[e0.x * 16 + sub];
                float a0 = __uint_as_float(e0.y);
                float2 l0 = __half22float2(*reinterpret_cast<__half2*>(&h0.x));
                float2 u0 = __half22float2(*reinterpret_cast<__half2*>(&h0.y));
                acc.x += a0 * l0.x; acc.y += a0 * l0.y;
                acc.z += a0 * u0.x; acc.w += a0 * u0.y;
            }
        }
        __syncwarp();
    }

    acc.x += __shfl_xor_sync(0xffffffffu, acc.x, 16);
    acc.y += __shfl_xor_sync(0xffffffffu, acc.y, 16);
    acc.z += __shfl_xor_sync(0xffffffffu, acc.z, 16);
    acc.w += __shfl_xor_sync(0xffffffffu, acc.w, 16);

#pragma unroll
    for (int off = 16; off > 0; off >>= 1)
        sum += __shfl_xor_sync(0xffffffffu, sum, off);
    float inv = 1.0f / (sum + 1e-9f);

    if (half == 0)
        reinterpret_cast<float4*>(&g_hneigh[v * 64 + sub * 4])[0] =
            make_float4(acc.x * inv, acc.y * inv, acc.z * inv, acc.w * inv);
}

// ---------------------------------------------------------------------------
// K6 (tiled SGEMM): 128x64 tile, 256 threads, 8x4 microtile.
// ---------------------------------------------------------------------------
__global__ void __launch_bounds__(256) k6_out(
    const float* __restrict__ feat,
    const float* __restrict__ W2w, const float* __restrict__ W2b,
    float* __restrict__ out, int N)
{
    __shared__ float ps[64][132];
    __shared__ float ws[64][68];
    __shared__ float biass[64];

    int t = threadIdx.x;
    int n0 = blockIdx.x * 128;

    for (int i = t; i < 1024; i += 256) {
        int r = i >> 4;
        int c4 = (i & 15) * 4;
        float4 wv = reinterpret_cast<const float4*>(W2w)[i];
        ws[c4 + 0][r] = wv.x; ws[c4 + 1][r] = wv.y;
        ws[c4 + 2][r] = wv.z; ws[c4 + 3][r] = wv.w;
    }
    for (int i = t; i < 2048; i += 256) {
        int r = i >> 4;
        int c4 = (i & 15) * 4;
        float4 fv = make_float4(0.f, 0.f, 0.f, 0.f);
        float4 hv = make_float4(0.f, 0.f, 0.f, 0.f);
        if (n0 + r < N) {
            fv = reinterpret_cast<const float4*>(feat)[(n0 + r) * 16 + (i & 15)];
            hv = reinterpret_cast<const float4*>(g_hneigh)[(n0 + r) * 16 + (i & 15)];
        }
        ps[c4 + 0][r] = fv.x * hv.x; ps[c4 + 1][r] = fv.y * hv.y;
        ps[c4 + 2][r] = fv.z * hv.z; ps[c4 + 3][r] = fv.w * hv.w;
    }
    if (t < 64) biass[t] = W2b[t];
    __syncthreads();

    int tx = t & 15, ty = t >> 4;
    float acc[8][4];
#pragma unroll
    for (int i = 0; i < 8; i++)
#pragma unroll
        for (int j = 0; j < 4; j++) acc[i][j] = biass[tx * 4 + j];

#pragma unroll 4
    for (int k = 0; k < 64; k++) {
        float4 b  = *reinterpret_cast<const float4*>(&ws[k][tx * 4]);
        float4 a0 = *reinterpret_cast<const float4*>(&ps[k][ty * 8]);
        float4 a1 = *reinterpret_cast<const float4*>(&ps[k][ty * 8 + 4]);
        float av[8] = {a0.x, a0.y, a0.z, a0.w, a1.x, a1.y, a1.z, a1.w};
#pragma unroll
        for (int i = 0; i < 8; i++) {
            acc[i][0] += av[i] * b.x; acc[i][1] += av[i] * b.y;
            acc[i][2] += av[i] * b.z; acc[i][3] += av[i] * b.w;
        }
    }

#pragma unroll
    for (int i = 0; i < 8; i++) {
        int n = n0 + ty * 8 + i;
        if (n < N) {
            float4 f = reinterpret_cast<const float4*>(feat)[n * 16 + tx];
            float4 h = reinterpret_cast<const float4*>(g_hneigh)[n * 16 + tx];
            float o0 = f.x + h.x + acc[i][0];
            float o1 = f.y + h.y + acc[i][1];
            float o2 = f.z + h.z + acc[i][2];
            float o3 = f.w + h.w + acc[i][3];
            o0 = (o0 > 0.f) ? o0 : 0.2f * o0;
            o1 = (o1 > 0.f) ? o1 : 0.2f * o1;
            o2 = (o2 > 0.f) ? o2 : 0.2f * o2;
            o3 = (o3 > 0.f) ? o3 : 0.2f * o3;
            reinterpret_cast<float4*>(out)[n * 16 + tx] = make_float4(o0, o1, o2, o3);
        }
    }
}

// ---------------------------------------------------------------------------
// Launch. Inputs identified by SIZE (robust to scalar materialization).
// ---------------------------------------------------------------------------
extern "C" void kernel_launch(void* const* d_in, const int* in_sizes, int n_in,
                              void* d_out, int out_size)
{
    const void  *idx = nullptr, *etype = nullptr;
    const float *feat = nullptr;
    const float *Wmat[3] = {nullptr, nullptr, nullptr};
    const float *Wb[3]   = {nullptr, nullptr, nullptr};
    const float *a = nullptr;
    int nm = 0, nb = 0;

    int big[8]; int nbig = 0;
    for (int i = 0; i < n_in; i++) {
        int s = in_sizes[i];
        if (s > 4096) { if (nbig < 8) big[nbig++] = i; }
        else if (s == 4096) { if (nm < 3) Wmat[nm++] = (const float*)d_in[i]; }
        else if (s == 128)  { a = (const float*)d_in[i]; }
        else if (s == 64)   { if (nb < 3) Wb[nb++] = (const float*)d_in[i]; }
    }
    for (int x = 0; x < nbig; x++)
        for (int y = 0; y < nbig; y++)
            if (x != y && in_sizes[big[x]] == 2 * in_sizes[big[y]]) {
                idx = d_in[big[x]]; etype = d_in[big[y]];
            }
    for (int x = 0; x < nbig; x++)
        if (d_in[big[x]] != idx && d_in[big[x]] != etype)
            feat = (const float*)d_in[big[x]];

    const float *W1w = Wmat[0], *W2w = Wmat[1], *Wattw = Wmat[2];
    const float *W1b = Wb[0],   *W2b = Wb[1],   *Wattb = Wb[2];

    int E = 0, N = 0;
    for (int x = 0; x < nbig; x++) {
        if (d_in[big[x]] == etype) E = in_sizes[big[x]];
        if ((const float*)d_in[big[x]] == feat) N = in_sizes[big[x]] / DD;
    }
    if (!idx || !etype || !feat || E <= 0 || N <= 0) return;

    int eb = (E + 255) / 256;
    int e2b = (E + 511) / 512;
    int gemb = (N + 127) / 128;
    int ntiles = (N + SCAN_TILE - 1) / SCAN_TILE;

    k1_node_pre<<<gemb, 256>>>(feat, W1w, W1b, Wattw, Wattb, a,
                               (const int*)idx, 2 * E, N);    // #1
    k2_hist<<<e2b, 256>>>(idx, E, N);                         // #2
    k4_scanfill<<<eb, 256>>>(idx, etype, E, N, ntiles);       // #3
    k5_gather<<<(N + 7) / 8, 256>>>(N);                       // #4 (profiled)
    k6_out<<<gemb, 256>>>(feat, W2w, W2b, (float*)d_out, N);  // #5
}